// round 4
// baseline (speedup 1.0000x reference)
#include <cuda_runtime.h>
#include <math.h>
#include <stdint.h>

#define B_   8
#define NTOK 512
#define NCTX 2048
#define EMBD 512
#define HH   8
#define DKV  64
#define EPSV 1e-6f

#define OUT_ELEMS ((size_t)B_ * NTOK * EMBD)

// ---------------- scratch ----------------------------------------------------
__device__ float g_q [B_ * HH * NTOK * DKV];   // [bh][t][d]
__device__ float g_k [B_ * HH * NCTX * DKV];   // [bh][c][d]
__device__ float g_v [B_ * HH * NCTX * DKV];   // [bh][c][d]
__device__ float g_qn [B_ * HH * NTOK];
__device__ float g_qnr[B_ * HH * NTOK];
__device__ float g_kn [B_ * HH * NCTX];
__device__ float g_knr[B_ * HH * NCTX];
__device__ float g_ho [B_ * NTOK * HH * DKV];  // [b][t][h][d]

// ---------------- helpers ----------------------------------------------------
__device__ __forceinline__ uint32_t f2tf(float x) {
    uint32_t r; asm("cvt.rna.tf32.f32 %0, %1;" : "=r"(r) : "f"(x)); return r;
}
__device__ __forceinline__ float tfr(float x) { return __uint_as_float(f2tf(x)); }

__device__ __forceinline__ void mma8(float* c, const uint32_t* a, const uint32_t* b) {
    asm volatile(
        "mma.sync.aligned.m16n8k8.row.col.f32.tf32.tf32.f32 "
        "{%0,%1,%2,%3}, {%4,%5,%6,%7}, {%8,%9}, {%0,%1,%2,%3};"
        : "+f"(c[0]), "+f"(c[1]), "+f"(c[2]), "+f"(c[3])
        : "r"(a[0]), "r"(a[1]), "r"(a[2]), "r"(a[3]), "r"(b[0]), "r"(b[1]));
}

__device__ __forceinline__ float fast_exp(float x)
{
    float t  = x * 1.4426950408889634f;
    float kf = rintf(t);
    float rr = fmaf(kf, -0.6931471805599453f, x);
    float p  = fmaf(rr, 0.0083333333f, 0.041666667f);
    p = fmaf(rr, p, 0.16666667f);
    p = fmaf(rr, p, 0.5f);
    p = fmaf(rr, p, 1.0f);
    p = fmaf(rr, p, 1.0f);
    return p * __int_as_float(((int)kf + 127) << 23);
}

// ---------------- projection GEMM (NT, mma.sync tf32) ------------------------
// D[m][n] = sum_k A[m][k] * B[n][k]
// MODE 0: C[m*N+n] = acc + bias[n]
// MODE 1: head scatter: C[((b*H+h)*ntok + t)*64 + d] = acc + bias[n]
// NORM: also emit per-(row,head) L2 norm + reciprocal
template <int MODE, bool NORM>
__global__ __launch_bounds__(256) void gemm_mma(
    const float* __restrict__ A, const float* __restrict__ Bm,
    const float* __restrict__ bias, float* __restrict__ C,
    float* __restrict__ nOut, float* __restrict__ rOut,
    int M, int N, int K, int ntok)
{
    constexpr int BM = 128, BN = 128;
    constexpr int ASTR = 20;
    __shared__ float As[2][BM * ASTR];
    __shared__ float Bs[2][BN * ASTR];

    const int tid  = threadIdx.x;
    const int wid  = tid >> 5;
    const int lane = tid & 31;
    const int r    = lane >> 2;
    const int cq   = lane & 3;
    const int wm   = wid & 3;
    const int wn   = wid >> 2;

    const int row0 = blockIdx.y * BM;
    const int col0 = blockIdx.x * BN;

    auto load_slab = [&](int buf, int k0) {
#pragma unroll
        for (int it = 0; it < 2; it++) {
            int row = (tid >> 2) + it * 64;
            int k4  = (tid & 3) * 4;
            float4 v = *(const float4*)(A + (size_t)(row0 + row) * K + k0 + k4);
            float* d = &As[buf][row * ASTR + k4];
            d[0] = tfr(v.x); d[1] = tfr(v.y); d[2] = tfr(v.z); d[3] = tfr(v.w);
            float4 w = *(const float4*)(Bm + (size_t)(col0 + row) * K + k0 + k4);
            float* e = &Bs[buf][row * ASTR + k4];
            e[0] = tfr(w.x); e[1] = tfr(w.y); e[2] = tfr(w.z); e[3] = tfr(w.w);
        }
    };

    float cr[2][8][4];
#pragma unroll
    for (int mt = 0; mt < 2; mt++)
#pragma unroll
        for (int nt = 0; nt < 8; nt++)
#pragma unroll
            for (int e = 0; e < 4; e++) cr[mt][nt][e] = 0.f;

    const int S = K >> 4;
    load_slab(0, 0);
    __syncthreads();

    for (int s = 0; s < S; s++) {
        if (s + 1 < S) load_slab((s + 1) & 1, (s + 1) * 16);
        const int buf = s & 1;
#pragma unroll
        for (int ks = 0; ks < 2; ks++) {
            uint32_t af[2][4];
#pragma unroll
            for (int mt = 0; mt < 2; mt++) {
                int mrow = wm * 32 + mt * 16 + r;
                af[mt][0] = __float_as_uint(As[buf][ mrow      * ASTR + ks * 8 + cq    ]);
                af[mt][1] = __float_as_uint(As[buf][(mrow + 8) * ASTR + ks * 8 + cq    ]);
                af[mt][2] = __float_as_uint(As[buf][ mrow      * ASTR + ks * 8 + cq + 4]);
                af[mt][3] = __float_as_uint(As[buf][(mrow + 8) * ASTR + ks * 8 + cq + 4]);
            }
            uint32_t bf[8][2];
#pragma unroll
            for (int nt = 0; nt < 8; nt++) {
                int nrow = wn * 64 + nt * 8 + r;
                bf[nt][0] = __float_as_uint(Bs[buf][nrow * ASTR + ks * 8 + cq    ]);
                bf[nt][1] = __float_as_uint(Bs[buf][nrow * ASTR + ks * 8 + cq + 4]);
            }
#pragma unroll
            for (int mt = 0; mt < 2; mt++)
#pragma unroll
                for (int nt = 0; nt < 8; nt++)
                    mma8(cr[mt][nt], af[mt], bf[nt]);
        }
        __syncthreads();
    }

    // -------- epilogue --------------------------------------------------------
#pragma unroll
    for (int mt = 0; mt < 2; mt++) {
        const int m1 = row0 + wm * 32 + mt * 16 + r;
        const int m2 = m1 + 8;
        float ss1 = 0.f, ss2 = 0.f;

#pragma unroll
        for (int nt = 0; nt < 8; nt++) {
            const int n = col0 + wn * 64 + nt * 8 + 2 * cq;
            float* cc = cr[mt][nt];
            float bx = bias[n], by = bias[n + 1];
            float v1x = cc[0] + bx, v1y = cc[1] + by;
            float v2x = cc[2] + bx, v2y = cc[3] + by;

            if constexpr (MODE == 0) {
                *(float2*)(C + (size_t)m1 * N + n) = make_float2(v1x, v1y);
                *(float2*)(C + (size_t)m2 * N + n) = make_float2(v2x, v2y);
            } else {
                int h = n >> 6, d0 = n & 63;
                int b1v = m1 / ntok, t1 = m1 - b1v * ntok;
                int b2v = m2 / ntok, t2 = m2 - b2v * ntok;
                *(float2*)(C + (((size_t)(b1v * HH + h)) * ntok + t1) * 64 + d0) =
                    make_float2(v1x, v1y);
                *(float2*)(C + (((size_t)(b2v * HH + h)) * ntok + t2) * 64 + d0) =
                    make_float2(v2x, v2y);
            }
            if (NORM) {
                ss1 = fmaf(v1x, v1x, fmaf(v1y, v1y, ss1));
                ss2 = fmaf(v2x, v2x, fmaf(v2y, v2y, ss2));
            }
        }
        if (NORM) {
            ss1 += __shfl_xor_sync(0xffffffffu, ss1, 1);
            ss1 += __shfl_xor_sync(0xffffffffu, ss1, 2);
            ss2 += __shfl_xor_sync(0xffffffffu, ss2, 1);
            ss2 += __shfl_xor_sync(0xffffffffu, ss2, 2);
            if (cq == 0) {
                int h = (col0 + wn * 64) >> 6;
                int b1v = m1 / ntok, t1 = m1 - b1v * ntok;
                int b2v = m2 / ntok, t2 = m2 - b2v * ntok;
                size_t i1 = ((size_t)(b1v * HH + h)) * ntok + t1;
                size_t i2 = ((size_t)(b2v * HH + h)) * ntok + t2;
                float n1 = sqrtf(ss1), n2 = sqrtf(ss2);
                nOut[i1] = n1; rOut[i1] = (n1 > 0.f) ? 1.0f / n1 : 0.f;
                nOut[i2] = n2; rOut[i2] = (n2 > 0.f) ? 1.0f / n2 : 0.f;
            }
        }
    }
}

// ---------------- fused attention: logits + exp + AV + normalize -------------
// SMEM float offsets
#define FQ_  0
#define FK_  (128 * 76)                 // 9728
#define FV_  (FK_ + 2 * 64 * 76)        // 19456
#define FP_  (FV_ + 2 * 64 * 72)        // 28672
#define FS_  (FP_ + 128 * 76)           // 38400
#define FTOT (FS_ + 128)                // 38528 floats = 154112 B

__global__ __launch_bounds__(256, 1) void attn_fused(
    const float* __restrict__ q, const float* __restrict__ k, const float* __restrict__ v,
    const float* __restrict__ qn, const float* __restrict__ qnr,
    const float* __restrict__ kn, const float* __restrict__ knr,
    float* __restrict__ att, float* __restrict__ ho)
{
    extern __shared__ float sm[];
    float* sQ = sm + FQ_;     // [128][76]
    float* sK = sm + FK_;     // [2][64][76]
    float* sV = sm + FV_;     // [2][64][72]
    float* sP = sm + FP_;     // [128][76]
    float* sS = sm + FS_;     // [128]

    const int tid  = threadIdx.x;
    const int wid  = tid >> 5;
    const int lane = tid & 31;
    const int r    = lane >> 2;
    const int cq   = lane & 3;
    const int wm   = wid & 3;
    const int wn   = wid >> 2;

    const int bh = blockIdx.y;
    const int t0 = blockIdx.x * 128;
    const int b  = bh >> 3, h = bh & 7;

    const float* Qp = q + ((size_t)bh * NTOK + t0) * 64;
    const float* Kp = k + (size_t)bh * NCTX * 64;
    const float* Vp = v + (size_t)bh * NCTX * 64;
    float* attp = att + ((size_t)bh * NTOK + t0) * NCTX;

    // load Q tile (tf32)
#pragma unroll
    for (int i = 0; i < 8; i++) {
        int idx = tid + i * 256;
        int row = idx >> 4, c4 = (idx & 15) * 4;
        float4 vv = *(const float4*)(Qp + (size_t)row * 64 + c4);
        float* d = &sQ[row * 76 + c4];
        d[0] = tfr(vv.x); d[1] = tfr(vv.y); d[2] = tfr(vv.z); d[3] = tfr(vv.w);
    }

    auto loadKV = [&](int buf, int c0) {
#pragma unroll
        for (int i = 0; i < 4; i++) {
            int idx = tid + i * 256;
            int row = idx >> 4, c4 = (idx & 15) * 4;
            float4 kk = *(const float4*)(Kp + (size_t)(c0 + row) * 64 + c4);
            float* d = &sK[buf * 4864 + row * 76 + c4];
            d[0] = tfr(kk.x); d[1] = tfr(kk.y); d[2] = tfr(kk.z); d[3] = tfr(kk.w);
            float4 vv = *(const float4*)(Vp + (size_t)(c0 + row) * 64 + c4);
            float* e = &sV[buf * 4608 + row * 72 + c4];
            e[0] = tfr(vv.x); e[1] = tfr(vv.y); e[2] = tfr(vv.z); e[3] = tfr(vv.w);
        }
    };
    loadKV(0, 0);

    // q-norm regs for owned rows
    float qnA[2], qrA[2], qnB[2], qrB[2];
#pragma unroll
    for (int mt = 0; mt < 2; mt++) {
        int m1 = wm * 32 + mt * 16 + r;
        qnA[mt] = qn [bh * NTOK + t0 + m1];
        qrA[mt] = qnr[bh * NTOK + t0 + m1];
        qnB[mt] = qn [bh * NTOK + t0 + m1 + 8];
        qrB[mt] = qnr[bh * NTOK + t0 + m1 + 8];
    }

    float av[2][4][4];
#pragma unroll
    for (int mt = 0; mt < 2; mt++)
#pragma unroll
        for (int nt = 0; nt < 4; nt++)
#pragma unroll
            for (int e = 0; e < 4; e++) av[mt][nt][e] = 0.f;
    float rsA[2] = {0.f, 0.f}, rsB[2] = {0.f, 0.f};

    __syncthreads();

    for (int ct = 0; ct < 32; ct++) {
        const int buf = ct & 1;
        if (ct + 1 < 32) loadKV(buf ^ 1, (ct + 1) * 64);

        // ---- MMA1: P = Q @ K^T ----
        float p[2][4][4];
#pragma unroll
        for (int mt = 0; mt < 2; mt++)
#pragma unroll
            for (int nt = 0; nt < 4; nt++)
#pragma unroll
                for (int e = 0; e < 4; e++) p[mt][nt][e] = 0.f;

#pragma unroll
        for (int ks = 0; ks < 8; ks++) {
            uint32_t af[2][4];
#pragma unroll
            for (int mt = 0; mt < 2; mt++) {
                int m1 = wm * 32 + mt * 16 + r;
                af[mt][0] = __float_as_uint(sQ[ m1      * 76 + ks * 8 + cq    ]);
                af[mt][1] = __float_as_uint(sQ[(m1 + 8) * 76 + ks * 8 + cq    ]);
                af[mt][2] = __float_as_uint(sQ[ m1      * 76 + ks * 8 + cq + 4]);
                af[mt][3] = __float_as_uint(sQ[(m1 + 8) * 76 + ks * 8 + cq + 4]);
            }
            uint32_t bf[4][2];
#pragma unroll
            for (int nt = 0; nt < 4; nt++) {
                int n = wn * 32 + nt * 8 + r;
                bf[nt][0] = __float_as_uint(sK[buf * 4864 + n * 76 + ks * 8 + cq    ]);
                bf[nt][1] = __float_as_uint(sK[buf * 4864 + n * 76 + ks * 8 + cq + 4]);
            }
#pragma unroll
            for (int mt = 0; mt < 2; mt++)
#pragma unroll
                for (int nt = 0; nt < 4; nt++)
                    mma8(p[mt][nt], af[mt], bf[nt]);
        }

        // ---- epilogue: cosine scale, exp, stage + stream out ----
#pragma unroll
        for (int mt = 0; mt < 2; mt++) {
            int m1 = wm * 32 + mt * 16 + r, m2 = m1 + 8;
#pragma unroll
            for (int nt = 0; nt < 4; nt++) {
                int nl = wn * 32 + nt * 8 + 2 * cq;
                int ng = ct * 64 + nl;
                float2 kv = *(const float2*)&kn [bh * NCTX + ng];
                float2 kr = *(const float2*)&knr[bh * NCTX + ng];
                float* cc = p[mt][nt];
                float i1x = (qnA[mt] * kv.x > EPSV) ? qrA[mt] * kr.x : 1e6f;
                float i1y = (qnA[mt] * kv.y > EPSV) ? qrA[mt] * kr.y : 1e6f;
                float i2x = (qnB[mt] * kv.x > EPSV) ? qrB[mt] * kr.x : 1e6f;
                float i2y = (qnB[mt] * kv.y > EPSV) ? qrB[mt] * kr.y : 1e6f;
                float e0 = fast_exp(cc[0] * i1x);
                float e1 = fast_exp(cc[1] * i1y);
                float e2 = fast_exp(cc[2] * i2x);
                float e3 = fast_exp(cc[3] * i2y);
                *(float2*)(attp + (size_t)m1 * NCTX + ng) = make_float2(e0, e1);
                *(float2*)(attp + (size_t)m2 * NCTX + ng) = make_float2(e2, e3);
                rsA[mt] += e0 + e1;
                rsB[mt] += e2 + e3;
                sP[m1 * 76 + nl] = tfr(e0); sP[m1 * 76 + nl + 1] = tfr(e1);
                sP[m2 * 76 + nl] = tfr(e2); sP[m2 * 76 + nl + 1] = tfr(e3);
            }
        }
        __syncthreads();

        // ---- MMA2: av += P @ V[buf] ----
#pragma unroll
        for (int ks = 0; ks < 8; ks++) {
            uint32_t af[2][4];
#pragma unroll
            for (int mt = 0; mt < 2; mt++) {
                int m1 = wm * 32 + mt * 16 + r;
                af[mt][0] = __float_as_uint(sP[ m1      * 76 + ks * 8 + cq    ]);
                af[mt][1] = __float_as_uint(sP[(m1 + 8) * 76 + ks * 8 + cq    ]);
                af[mt][2] = __float_as_uint(sP[ m1      * 76 + ks * 8 + cq + 4]);
                af[mt][3] = __float_as_uint(sP[(m1 + 8) * 76 + ks * 8 + cq + 4]);
            }
            uint32_t bf[4][2];
#pragma unroll
            for (int nt = 0; nt < 4; nt++) {
                int n = wn * 32 + nt * 8 + r;
                bf[nt][0] = __float_as_uint(sV[buf * 4608 + (ks * 8 + cq    ) * 72 + n]);
                bf[nt][1] = __float_as_uint(sV[buf * 4608 + (ks * 8 + cq + 4) * 72 + n]);
            }
#pragma unroll
            for (int mt = 0; mt < 2; mt++)
#pragma unroll
                for (int nt = 0; nt < 4; nt++)
                    mma8(av[mt][nt], af[mt], bf[nt]);
        }
        __syncthreads();
    }

    // ---- row sums: quad reduce then cross-wn via SMEM ----
#pragma unroll
    for (int mt = 0; mt < 2; mt++) {
        rsA[mt] += __shfl_xor_sync(0xffffffffu, rsA[mt], 1);
        rsA[mt] += __shfl_xor_sync(0xffffffffu, rsA[mt], 2);
        rsB[mt] += __shfl_xor_sync(0xffffffffu, rsB[mt], 1);
        rsB[mt] += __shfl_xor_sync(0xffffffffu, rsB[mt], 2);
    }
    if (wn == 0 && cq == 0) {
#pragma unroll
        for (int mt = 0; mt < 2; mt++) {
            int m1 = wm * 32 + mt * 16 + r;
            sS[m1] = rsA[mt];
            sS[m1 + 8] = rsB[mt];
        }
    }
    __syncthreads();
    if (wn == 1 && cq == 0) {
#pragma unroll
        for (int mt = 0; mt < 2; mt++) {
            int m1 = wm * 32 + mt * 16 + r;
            sS[m1] += rsA[mt];
            sS[m1 + 8] += rsB[mt];
        }
    }
    __syncthreads();
    if (tid < 128) sS[tid] = 1.0f / sS[tid];
    __syncthreads();

    // ---- write normalized AV -> ho [b][t][h][d] ----
#pragma unroll
    for (int mt = 0; mt < 2; mt++) {
        int m1 = wm * 32 + mt * 16 + r, m2 = m1 + 8;
        float iA = sS[m1], iB = sS[m2];
#pragma unroll
        for (int nt = 0; nt < 4; nt++) {
            int d0 = wn * 32 + nt * 8 + 2 * cq;
            float* cc = av[mt][nt];
            *(float2*)(g_ho + (((size_t)(b * NTOK + t0 + m1)) * HH + h) * 64 + d0) =
                make_float2(cc[0] * iA, cc[1] * iA);
            *(float2*)(g_ho + (((size_t)(b * NTOK + t0 + m2)) * HH + h) * 64 + d0) =
                make_float2(cc[2] * iB, cc[3] * iB);
        }
    }

    // ---- phase 2: normalize att slice in place (L2-warm) ----
#pragma unroll 4
    for (int i = 0; i < 256; i++) {
        int idx = tid + i * 256;          // float4 index over 128*2048/4
        int row = idx >> 9;
        float inv = sS[row];
        float4* pp = (float4*)attp + idx;
        float4 vv = *pp;
        vv.x *= inv; vv.y *= inv; vv.z *= inv; vv.w *= inv;
        *pp = vv;
    }
}

// ---------------- launch -----------------------------------------------------
extern "C" void kernel_launch(void* const* d_in, const int* in_sizes, int n_in,
                              void* d_out, int out_size)
{
    const float* queries = (const float*)d_in[0];
    const float* keys    = (const float*)d_in[1];
    const float* values  = (const float*)d_in[2];
    const float* W_At    = (const float*)d_in[3];
    const float* b_At    = (const float*)d_in[4];
    const float* W_Ac    = (const float*)d_in[5];
    const float* b_Ac    = (const float*)d_in[6];
    const float* W_Bc    = (const float*)d_in[7];
    const float* b_Bc    = (const float*)d_in[8];
    const float* W_R     = (const float*)d_in[9];
    const float* b_R     = (const float*)d_in[10];

    float* out = (float*)d_out;
    float* att = out + OUT_ELEMS;

    float *q, *k, *v, *ho, *qn, *qnr, *kn, *knr;
    cudaGetSymbolAddress((void**)&q,   g_q);
    cudaGetSymbolAddress((void**)&k,   g_k);
    cudaGetSymbolAddress((void**)&v,   g_v);
    cudaGetSymbolAddress((void**)&ho,  g_ho);
    cudaGetSymbolAddress((void**)&qn,  g_qn);
    cudaGetSymbolAddress((void**)&qnr, g_qnr);
    cudaGetSymbolAddress((void**)&kn,  g_kn);
    cudaGetSymbolAddress((void**)&knr, g_knr);

    const int SMEMB = FTOT * 4;
    cudaFuncSetAttribute(attn_fused, cudaFuncAttributeMaxDynamicSharedMemorySize, SMEMB);

    // projections (with fused norms for Q/K)
    gemm_mma<1, true ><<<dim3(4, 32),  256>>>(queries, W_At, b_At, q, qn, qnr, B_ * NTOK, HH * DKV, EMBD, NTOK);
    gemm_mma<1, true ><<<dim3(4, 128), 256>>>(keys,    W_Ac, b_Ac, k, kn, knr, B_ * NCTX, HH * DKV, EMBD, NCTX);
    gemm_mma<1, false><<<dim3(4, 128), 256>>>(values,  W_Bc, b_Bc, v, nullptr, nullptr, B_ * NCTX, HH * DKV, EMBD, NCTX);

    // fused attention (logits + exp + AV + in-place normalize)
    attn_fused<<<dim3(4, 64), 256, SMEMB>>>(q, k, v, qn, qnr, kn, knr, att, ho);

    // output projection
    gemm_mma<0, false><<<dim3(4, 32), 256>>>(ho, W_R, b_R, out, nullptr, nullptr, B_ * NTOK, EMBD, HH * DKV, 0);
}

// round 5
// speedup vs baseline: 1.8125x; 1.8125x over previous
#include <cuda_runtime.h>
#include <cuda_fp16.h>
#include <math.h>
#include <stdint.h>

#define B_   8
#define NTOK 512
#define NCTX 2048
#define EMBD 512
#define HH   8
#define DKV  64
#define EPSV 1e-6f

#define OUT_ELEMS ((size_t)B_ * NTOK * EMBD)

// ---------------- scratch (fp16 q/k/v halves the attention traffic) ----------
__device__ __half g_q [B_ * HH * NTOK * DKV];
__device__ __half g_k [B_ * HH * NCTX * DKV];
__device__ __half g_v [B_ * HH * NCTX * DKV];
__device__ float  g_qn [B_ * HH * NTOK];
__device__ float  g_qnr[B_ * HH * NTOK];
__device__ float  g_kn [B_ * HH * NCTX];
__device__ float  g_knr[B_ * HH * NCTX];
__device__ float  g_ho [B_ * NTOK * HH * DKV];

// ---------------- ptx helpers -------------------------------------------------
__device__ __forceinline__ void ldsm4(uint32_t* d, uint32_t addr) {
    asm volatile("ldmatrix.sync.aligned.m8n8.x4.shared.b16 {%0,%1,%2,%3}, [%4];"
        : "=r"(d[0]), "=r"(d[1]), "=r"(d[2]), "=r"(d[3]) : "r"(addr));
}
__device__ __forceinline__ void ldsm4t(uint32_t* d, uint32_t addr) {
    asm volatile("ldmatrix.sync.aligned.m8n8.x4.trans.shared.b16 {%0,%1,%2,%3}, [%4];"
        : "=r"(d[0]), "=r"(d[1]), "=r"(d[2]), "=r"(d[3]) : "r"(addr));
}
__device__ __forceinline__ void mma16(float* c, const uint32_t* a, const uint32_t* b) {
    asm volatile(
        "mma.sync.aligned.m16n8k16.row.col.f32.f16.f16.f32 "
        "{%0,%1,%2,%3}, {%4,%5,%6,%7}, {%8,%9}, {%0,%1,%2,%3};"
        : "+f"(c[0]), "+f"(c[1]), "+f"(c[2]), "+f"(c[3])
        : "r"(a[0]), "r"(a[1]), "r"(a[2]), "r"(a[3]), "r"(b[0]), "r"(b[1]));
}
__device__ __forceinline__ float fast_exp(float x)
{
    float t  = x * 1.4426950408889634f;
    float kf = rintf(t);
    float rr = fmaf(kf, -0.6931471805599453f, x);
    float p  = fmaf(rr, 0.0083333333f, 0.041666667f);
    p = fmaf(rr, p, 0.16666667f);
    p = fmaf(rr, p, 0.5f);
    p = fmaf(rr, p, 1.0f);
    p = fmaf(rr, p, 1.0f);
    return p * __int_as_float(((int)kf + 127) << 23);
}
__device__ __forceinline__ void pack8(__half2* d, float4 a, float4 b) {
    d[0] = __floats2half2_rn(a.x, a.y); d[1] = __floats2half2_rn(a.z, a.w);
    d[2] = __floats2half2_rn(b.x, b.y); d[3] = __floats2half2_rn(b.z, b.w);
}

// ---------------- fp16 NT GEMM: D = A(MxK) * B(NxK)^T + bias ------------------
// MODE 0: C float [m*N+n]
// MODE 1: head scatter to __half C[((b*H+h)*ntok + t)*64 + d]; NORM: emit norms
template <int MODE, bool NORM>
__global__ __launch_bounds__(256, 2) void gemm_f16(
    const float* __restrict__ A, const float* __restrict__ Bm,
    const float* __restrict__ bias, void* __restrict__ Cv,
    float* __restrict__ nOut, float* __restrict__ rOut,
    int M, int N, int K, int ntok)
{
    constexpr int SA = 40;                      // halfs stride (80B) — ldsm conflict-free
    __shared__ __half As[2][128 * SA];
    __shared__ __half Bs[2][128 * SA];

    const int tid  = threadIdx.x;
    const int wid  = tid >> 5;
    const int lane = tid & 31;
    const int r    = lane >> 2;
    const int cq   = lane & 3;
    const int wm   = wid & 3;
    const int wn   = wid >> 2;
    const int row0 = blockIdx.y * 128;
    const int col0 = blockIdx.x * 128;

    const int lr  = lane & 7, grp = lane >> 3;
    const int aRO = ((grp & 1) << 3) + lr, aKO = (grp >> 1) << 3;
    const int bRO = ((grp >> 1) << 3) + lr, bKO = (grp & 1) << 3;

    auto ld_slab = [&](int buf, int k0) {
        int row = tid >> 1;
        int seg = (tid & 1) << 4;
        const float* pa = A + (size_t)(row0 + row) * K + k0 + seg;
        float4 x0 = *(const float4*)pa,       x1 = *(const float4*)(pa + 4);
        float4 x2 = *(const float4*)(pa + 8), x3 = *(const float4*)(pa + 12);
        __half2* d = (__half2*)&As[buf][row * SA + seg];
        pack8(d, x0, x1); pack8(d + 4, x2, x3);
        const float* pb = Bm + (size_t)(col0 + row) * K + k0 + seg;
        float4 y0 = *(const float4*)pb,       y1 = *(const float4*)(pb + 4);
        float4 y2 = *(const float4*)(pb + 8), y3 = *(const float4*)(pb + 12);
        __half2* e = (__half2*)&Bs[buf][row * SA + seg];
        pack8(e, y0, y1); pack8(e + 4, y2, y3);
    };

    float cr[2][8][4];
#pragma unroll
    for (int mt = 0; mt < 2; mt++)
#pragma unroll
        for (int nt = 0; nt < 8; nt++)
#pragma unroll
            for (int e = 0; e < 4; e++) cr[mt][nt][e] = 0.f;

    const uint32_t asB = (uint32_t)__cvta_generic_to_shared(&As[0][0]);
    const uint32_t bsB = (uint32_t)__cvta_generic_to_shared(&Bs[0][0]);

    const int S = K >> 5;
    ld_slab(0, 0);
    __syncthreads();

    for (int s = 0; s < S; s++) {
        if (s + 1 < S) ld_slab((s + 1) & 1, (s + 1) * 32);
        const int buf = s & 1;
        const uint32_t aO = asB + buf * (128 * SA * 2);
        const uint32_t bO = bsB + buf * (128 * SA * 2);
#pragma unroll
        for (int k16 = 0; k16 < 2; k16++) {
            uint32_t af[2][4];
#pragma unroll
            for (int mt = 0; mt < 2; mt++)
                ldsm4(af[mt], aO + ((wm * 32 + mt * 16 + aRO) * SA + k16 * 16 + aKO) * 2);
            uint32_t bf[8][2];
#pragma unroll
            for (int ntp = 0; ntp < 4; ntp++) {
                uint32_t t[4];
                ldsm4(t, bO + ((wn * 64 + ntp * 16 + bRO) * SA + k16 * 16 + bKO) * 2);
                bf[2 * ntp][0] = t[0]; bf[2 * ntp][1] = t[1];
                bf[2 * ntp + 1][0] = t[2]; bf[2 * ntp + 1][1] = t[3];
            }
#pragma unroll
            for (int mt = 0; mt < 2; mt++)
#pragma unroll
                for (int nt = 0; nt < 8; nt++)
                    mma16(cr[mt][nt], af[mt], bf[nt]);
        }
        __syncthreads();
    }

    // -------- epilogue --------------------------------------------------------
#pragma unroll
    for (int mt = 0; mt < 2; mt++) {
        const int m1 = row0 + wm * 32 + mt * 16 + r;
        const int m2 = m1 + 8;
        float ss1 = 0.f, ss2 = 0.f;
#pragma unroll
        for (int nt = 0; nt < 8; nt++) {
            const int n = col0 + wn * 64 + nt * 8 + 2 * cq;
            float* cc = cr[mt][nt];
            float bx = bias[n], by = bias[n + 1];
            float v1x = cc[0] + bx, v1y = cc[1] + by;
            float v2x = cc[2] + bx, v2y = cc[3] + by;
            if constexpr (MODE == 0) {
                float* C = (float*)Cv;
                *(float2*)(C + (size_t)m1 * N + n) = make_float2(v1x, v1y);
                *(float2*)(C + (size_t)m2 * N + n) = make_float2(v2x, v2y);
            } else {
                __half* C = (__half*)Cv;
                int h = n >> 6, d0 = n & 63;
                int b1v = m1 / ntok, t1 = m1 - b1v * ntok;
                int b2v = m2 / ntok, t2 = m2 - b2v * ntok;
                __half2 h1 = __floats2half2_rn(v1x, v1y);
                __half2 h2 = __floats2half2_rn(v2x, v2y);
                *(__half2*)(C + (((size_t)(b1v * HH + h)) * ntok + t1) * 64 + d0) = h1;
                *(__half2*)(C + (((size_t)(b2v * HH + h)) * ntok + t2) * 64 + d0) = h2;
                if (NORM) {
                    float r1x = __half2float(__low2half(h1)), r1y = __half2float(__high2half(h1));
                    float r2x = __half2float(__low2half(h2)), r2y = __half2float(__high2half(h2));
                    ss1 = fmaf(r1x, r1x, fmaf(r1y, r1y, ss1));
                    ss2 = fmaf(r2x, r2x, fmaf(r2y, r2y, ss2));
                }
            }
        }
        if (NORM) {
            ss1 += __shfl_xor_sync(0xffffffffu, ss1, 1);
            ss1 += __shfl_xor_sync(0xffffffffu, ss1, 2);
            ss2 += __shfl_xor_sync(0xffffffffu, ss2, 1);
            ss2 += __shfl_xor_sync(0xffffffffu, ss2, 2);
            if (cq == 0) {
                int h = (col0 + wn * 64) >> 6;
                int b1v = m1 / ntok, t1 = m1 - b1v * ntok;
                int b2v = m2 / ntok, t2 = m2 - b2v * ntok;
                size_t i1 = ((size_t)(b1v * HH + h)) * ntok + t1;
                size_t i2 = ((size_t)(b2v * HH + h)) * ntok + t2;
                float n1 = sqrtf(ss1), n2 = sqrtf(ss2);
                nOut[i1] = n1; rOut[i1] = (n1 > 0.f) ? 1.0f / n1 : 0.f;
                nOut[i2] = n2; rOut[i2] = (n2 > 0.f) ? 1.0f / n2 : 0.f;
            }
        }
    }
}

// ---------------- fused attention (fp16, two-pass, att written once) ----------
#define AS 72                              // halfs stride (144B) — ldsm conflict-free
#define SQ_OFF 0
#define SK_OFF (128 * AS)                  // 2 bufs of 64*AS
#define SV_OFF (SK_OFF + 2 * 64 * AS)
#define SP_OFF (SV_OFF + 2 * 64 * AS)
#define SS_OFF (SP_OFF + 128 * AS)         // float[128] after this (half idx)
#define SMEM_HALFS (SS_OFF)
#define ATTN_SMEM (SMEM_HALFS * 2 + 128 * 4)

__global__ __launch_bounds__(256, 2) void attn_fused(
    const __half* __restrict__ q, const __half* __restrict__ k, const __half* __restrict__ v,
    const float* __restrict__ qn, const float* __restrict__ qnr,
    const float* __restrict__ kn, const float* __restrict__ knr,
    float* __restrict__ att, float* __restrict__ ho)
{
    extern __shared__ __half smh[];
    __half* sQ = smh + SQ_OFF;
    __half* sK = smh + SK_OFF;
    __half* sV = smh + SV_OFF;
    __half* sP = smh + SP_OFF;
    float*  sS = (float*)(smh + SS_OFF);

    const int tid  = threadIdx.x;
    const int wid  = tid >> 5;
    const int lane = tid & 31;
    const int r    = lane >> 2;
    const int cq   = lane & 3;
    const int wm   = wid & 3;
    const int wn   = wid >> 2;

    const int bh = blockIdx.y;
    const int t0 = blockIdx.x * 128;
    const int b  = bh >> 3, h = bh & 7;

    const __half* Qp = q + ((size_t)bh * NTOK + t0) * 64;
    const __half* Kp = k + (size_t)bh * NCTX * 64;
    const __half* Vp = v + (size_t)bh * NCTX * 64;
    float* attp = att + ((size_t)bh * NTOK + t0) * NCTX;

    const uint32_t sQb = (uint32_t)__cvta_generic_to_shared(sQ);
    const uint32_t sKb = (uint32_t)__cvta_generic_to_shared(sK);
    const uint32_t sVb = (uint32_t)__cvta_generic_to_shared(sV);
    const uint32_t sPb = (uint32_t)__cvta_generic_to_shared(sP);

    const int lr  = lane & 7, grp = lane >> 3;
    const int aRO = ((grp & 1) << 3) + lr, aKO = (grp >> 1) << 3;   // A (sQ/sP)
    const int bRO = ((grp >> 1) << 3) + lr, bKO = (grp & 1) << 3;   // B (sK)
    const int vRO = ((grp & 1) << 3) + lr, vDO = (grp >> 1) << 3;   // B trans (sV)

    // load Q tile: 1024 16B-chunks
#pragma unroll
    for (int i = 0; i < 4; i++) {
        int c = tid + i * 256;
        int row = c >> 3, off = (c & 7) * 8;
        *(uint4*)&sQ[row * AS + off] = *(const uint4*)(Qp + (size_t)row * 64 + off);
    }
    auto loadK = [&](int buf, int c0) {
#pragma unroll
        for (int i = 0; i < 2; i++) {
            int c = tid + i * 256;
            int row = c >> 3, off = (c & 7) * 8;
            *(uint4*)&sK[buf * 64 * AS + row * AS + off] =
                *(const uint4*)(Kp + (size_t)(c0 + row) * 64 + off);
        }
    };
    auto loadV = [&](int buf, int c0) {
#pragma unroll
        for (int i = 0; i < 2; i++) {
            int c = tid + i * 256;
            int row = c >> 3, off = (c & 7) * 8;
            *(uint4*)&sV[buf * 64 * AS + row * AS + off] =
                *(const uint4*)(Vp + (size_t)(c0 + row) * 64 + off);
        }
    };

    // q norms for owned rows
    float qnA[2], qrA[2], qnB[2], qrB[2];
#pragma unroll
    for (int mt = 0; mt < 2; mt++) {
        int m1 = wm * 32 + mt * 16 + r;
        qnA[mt] = qn [bh * NTOK + t0 + m1];
        qrA[mt] = qnr[bh * NTOK + t0 + m1];
        qnB[mt] = qn [bh * NTOK + t0 + m1 + 8];
        qrB[mt] = qnr[bh * NTOK + t0 + m1 + 8];
    }

    // MMA1: p = Q @ K^T for one 64-col tile
    auto mma1 = [&](int buf, float p[2][4][4]) {
#pragma unroll
        for (int mt = 0; mt < 2; mt++)
#pragma unroll
            for (int nt = 0; nt < 4; nt++)
#pragma unroll
                for (int e = 0; e < 4; e++) p[mt][nt][e] = 0.f;
        const uint32_t kO = sKb + buf * (64 * AS * 2);
#pragma unroll
        for (int k16 = 0; k16 < 4; k16++) {
            uint32_t af[2][4];
#pragma unroll
            for (int mt = 0; mt < 2; mt++)
                ldsm4(af[mt], sQb + ((wm * 32 + mt * 16 + aRO) * AS + k16 * 16 + aKO) * 2);
            uint32_t bf[4][2];
#pragma unroll
            for (int ntp = 0; ntp < 2; ntp++) {
                uint32_t t[4];
                ldsm4(t, kO + ((wn * 32 + ntp * 16 + bRO) * AS + k16 * 16 + bKO) * 2);
                bf[2 * ntp][0] = t[0]; bf[2 * ntp][1] = t[1];
                bf[2 * ntp + 1][0] = t[2]; bf[2 * ntp + 1][1] = t[3];
            }
#pragma unroll
            for (int mt = 0; mt < 2; mt++)
#pragma unroll
                for (int nt = 0; nt < 4; nt++)
                    mma16(p[mt][nt], af[mt], bf[nt]);
        }
    };

    float rsA[2] = {0.f, 0.f}, rsB[2] = {0.f, 0.f};

    // ================= pass 1: row sums only =================
    loadK(0, 0);
    __syncthreads();
    for (int ct = 0; ct < 32; ct++) {
        const int buf = ct & 1;
        if (ct + 1 < 32) loadK(buf ^ 1, (ct + 1) * 64);
        float p[2][4][4];
        mma1(buf, p);
#pragma unroll
        for (int mt = 0; mt < 2; mt++) {
#pragma unroll
            for (int nt = 0; nt < 4; nt++) {
                int nl = wn * 32 + nt * 8 + 2 * cq;
                int ng = ct * 64 + nl;
                float2 kv = *(const float2*)(kn  + bh * NCTX + ng);
                float2 kr = *(const float2*)(knr + bh * NCTX + ng);
                float* cc = p[mt][nt];
                float i1x = (qnA[mt] * kv.x > EPSV) ? qrA[mt] * kr.x : 1e6f;
                float i1y = (qnA[mt] * kv.y > EPSV) ? qrA[mt] * kr.y : 1e6f;
                float i2x = (qnB[mt] * kv.x > EPSV) ? qrB[mt] * kr.x : 1e6f;
                float i2y = (qnB[mt] * kv.y > EPSV) ? qrB[mt] * kr.y : 1e6f;
                rsA[mt] += fast_exp(cc[0] * i1x) + fast_exp(cc[1] * i1y);
                rsB[mt] += fast_exp(cc[2] * i2x) + fast_exp(cc[3] * i2y);
            }
        }
        __syncthreads();
    }

    // ---- reduce row sums -> sS = 1/sum ----
#pragma unroll
    for (int mt = 0; mt < 2; mt++) {
        rsA[mt] += __shfl_xor_sync(0xffffffffu, rsA[mt], 1);
        rsA[mt] += __shfl_xor_sync(0xffffffffu, rsA[mt], 2);
        rsB[mt] += __shfl_xor_sync(0xffffffffu, rsB[mt], 1);
        rsB[mt] += __shfl_xor_sync(0xffffffffu, rsB[mt], 2);
    }
    if (wn == 0 && cq == 0) {
#pragma unroll
        for (int mt = 0; mt < 2; mt++) {
            int m1 = wm * 32 + mt * 16 + r;
            sS[m1] = rsA[mt]; sS[m1 + 8] = rsB[mt];
        }
    }
    __syncthreads();
    if (wn == 1 && cq == 0) {
#pragma unroll
        for (int mt = 0; mt < 2; mt++) {
            int m1 = wm * 32 + mt * 16 + r;
            sS[m1] += rsA[mt]; sS[m1 + 8] += rsB[mt];
        }
    }
    __syncthreads();
    if (tid < 128) sS[tid] = 1.0f / sS[tid];
    __syncthreads();

    float invA[2], invB[2];
#pragma unroll
    for (int mt = 0; mt < 2; mt++) {
        int m1 = wm * 32 + mt * 16 + r;
        invA[mt] = sS[m1]; invB[mt] = sS[m1 + 8];
    }

    // ================= pass 2: write att once + AV =================
    float av[2][4][4];
#pragma unroll
    for (int mt = 0; mt < 2; mt++)
#pragma unroll
        for (int nt = 0; nt < 4; nt++)
#pragma unroll
            for (int e = 0; e < 4; e++) av[mt][nt][e] = 0.f;

    loadK(0, 0); loadV(0, 0);
    __syncthreads();

    for (int ct = 0; ct < 32; ct++) {
        const int buf = ct & 1;
        if (ct + 1 < 32) { loadK(buf ^ 1, (ct + 1) * 64); loadV(buf ^ 1, (ct + 1) * 64); }
        float p[2][4][4];
        mma1(buf, p);

#pragma unroll
        for (int mt = 0; mt < 2; mt++) {
            int m1 = wm * 32 + mt * 16 + r, m2 = m1 + 8;
#pragma unroll
            for (int nt = 0; nt < 4; nt++) {
                int nl = wn * 32 + nt * 8 + 2 * cq;
                int ng = ct * 64 + nl;
                float2 kv = *(const float2*)(kn  + bh * NCTX + ng);
                float2 kr = *(const float2*)(knr + bh * NCTX + ng);
                float* cc = p[mt][nt];
                float i1x = (qnA[mt] * kv.x > EPSV) ? qrA[mt] * kr.x : 1e6f;
                float i1y = (qnA[mt] * kv.y > EPSV) ? qrA[mt] * kr.y : 1e6f;
                float i2x = (qnB[mt] * kv.x > EPSV) ? qrB[mt] * kr.x : 1e6f;
                float i2y = (qnB[mt] * kv.y > EPSV) ? qrB[mt] * kr.y : 1e6f;
                float e0 = fast_exp(cc[0] * i1x);
                float e1 = fast_exp(cc[1] * i1y);
                float e2 = fast_exp(cc[2] * i2x);
                float e3 = fast_exp(cc[3] * i2y);
                __stcs((float2*)(attp + (size_t)m1 * NCTX + ng),
                       make_float2(e0 * invA[mt], e1 * invA[mt]));
                __stcs((float2*)(attp + (size_t)m2 * NCTX + ng),
                       make_float2(e2 * invB[mt], e3 * invB[mt]));
                *(__half2*)&sP[m1 * AS + nl] = __floats2half2_rn(e0, e1);
                *(__half2*)&sP[m2 * AS + nl] = __floats2half2_rn(e2, e3);
            }
        }
        __syncthreads();

        // MMA2: av += P @ V[buf]
        const uint32_t vO = sVb + buf * (64 * AS * 2);
#pragma unroll
        for (int k16 = 0; k16 < 4; k16++) {
            uint32_t af[2][4];
#pragma unroll
            for (int mt = 0; mt < 2; mt++)
                ldsm4(af[mt], sPb + ((wm * 32 + mt * 16 + aRO) * AS + k16 * 16 + aKO) * 2);
            uint32_t bf[4][2];
#pragma unroll
            for (int ntp = 0; ntp < 2; ntp++) {
                uint32_t t[4];
                ldsm4t(t, vO + ((k16 * 16 + vRO) * AS + wn * 32 + ntp * 16 + vDO) * 2);
                bf[2 * ntp][0] = t[0]; bf[2 * ntp][1] = t[1];
                bf[2 * ntp + 1][0] = t[2]; bf[2 * ntp + 1][1] = t[3];
            }
#pragma unroll
            for (int mt = 0; mt < 2; mt++)
#pragma unroll
                for (int nt = 0; nt < 4; nt++)
                    mma16(av[mt][nt], af[mt], bf[nt]);
        }
        __syncthreads();
    }

    // ---- write normalized AV -> ho [b][t][h][d] ----
#pragma unroll
    for (int mt = 0; mt < 2; mt++) {
        int m1 = wm * 32 + mt * 16 + r, m2 = m1 + 8;
#pragma unroll
        for (int nt = 0; nt < 4; nt++) {
            int d0 = wn * 32 + nt * 8 + 2 * cq;
            float* cc = av[mt][nt];
            *(float2*)(ho + (((size_t)(b * NTOK + t0 + m1)) * HH + h) * 64 + d0) =
                make_float2(cc[0] * invA[mt], cc[1] * invA[mt]);
            *(float2*)(ho + (((size_t)(b * NTOK + t0 + m2)) * HH + h) * 64 + d0) =
                make_float2(cc[2] * invB[mt], cc[3] * invB[mt]);
        }
    }
}

// ---------------- launch -----------------------------------------------------
extern "C" void kernel_launch(void* const* d_in, const int* in_sizes, int n_in,
                              void* d_out, int out_size)
{
    const float* queries = (const float*)d_in[0];
    const float* keys    = (const float*)d_in[1];
    const float* values  = (const float*)d_in[2];
    const float* W_At    = (const float*)d_in[3];
    const float* b_At    = (const float*)d_in[4];
    const float* W_Ac    = (const float*)d_in[5];
    const float* b_Ac    = (const float*)d_in[6];
    const float* W_Bc    = (const float*)d_in[7];
    const float* b_Bc    = (const float*)d_in[8];
    const float* W_R     = (const float*)d_in[9];
    const float* b_R     = (const float*)d_in[10];

    float* out = (float*)d_out;
    float* att = out + OUT_ELEMS;

    __half *q, *k, *v;
    float *ho, *qn, *qnr, *kn, *knr;
    cudaGetSymbolAddress((void**)&q,   g_q);
    cudaGetSymbolAddress((void**)&k,   g_k);
    cudaGetSymbolAddress((void**)&v,   g_v);
    cudaGetSymbolAddress((void**)&ho,  g_ho);
    cudaGetSymbolAddress((void**)&qn,  g_qn);
    cudaGetSymbolAddress((void**)&qnr, g_qnr);
    cudaGetSymbolAddress((void**)&kn,  g_kn);
    cudaGetSymbolAddress((void**)&knr, g_knr);

    cudaFuncSetAttribute(attn_fused, cudaFuncAttributeMaxDynamicSharedMemorySize, ATTN_SMEM);

    // projections (fp16 outputs; norms fused for Q/K)
    gemm_f16<1, true ><<<dim3(4, 32),  256>>>(queries, W_At, b_At, q, qn, qnr, B_ * NTOK, HH * DKV, EMBD, NTOK);
    gemm_f16<1, true ><<<dim3(4, 128), 256>>>(keys,    W_Ac, b_Ac, k, kn, knr, B_ * NCTX, HH * DKV, EMBD, NCTX);
    gemm_f16<1, false><<<dim3(4, 128), 256>>>(values,  W_Bc, b_Bc, v, nullptr, nullptr, B_ * NCTX, HH * DKV, EMBD, NCTX);

    // fused attention: pass1 sums, pass2 single normalized att write + AV
    attn_fused<<<dim3(4, 64), 256, ATTN_SMEM>>>(q, k, v, qn, qnr, kn, knr, att, ho);

    // output projection (fp32 A path)
    gemm_f16<0, false><<<dim3(4, 32), 256>>>(ho, W_R, b_R, out, nullptr, nullptr, B_ * NTOK, EMBD, HH * DKV, 0);
}

// round 8
// speedup vs baseline: 2.2621x; 1.2480x over previous
#include <cuda_runtime.h>
#include <cuda_fp16.h>
#include <math.h>
#include <stdint.h>

#define B_   8
#define NTOK 512
#define NCTX 2048
#define EMBD 512
#define HH   8
#define DKV  64
#define EPSV 1e-6f

#define OUT_ELEMS ((size_t)B_ * NTOK * EMBD)

// ---------------- scratch -----------------------------------------------------
__device__ __half g_xq[B_ * NTOK * EMBD];
__device__ __half g_xk[B_ * NCTX * EMBD];
__device__ __half g_xv[B_ * NCTX * EMBD];
__device__ __half g_wat[EMBD * EMBD], g_wac[EMBD * EMBD], g_wbc[EMBD * EMBD], g_wr[EMBD * EMBD];
__device__ __half g_q [B_ * HH * NTOK * DKV];
__device__ __half g_k [B_ * HH * NCTX * DKV];
__device__ __half g_v [B_ * HH * NCTX * DKV];
__device__ __half g_ho[B_ * NTOK * HH * DKV];
__device__ float  g_qn [B_ * HH * NTOK];
__device__ float  g_qnr[B_ * HH * NTOK];
__device__ float  g_kn [B_ * HH * NCTX];
__device__ float  g_knr[B_ * HH * NCTX];

// ---------------- ptx helpers -------------------------------------------------
__device__ __forceinline__ void cp16(uint32_t dst, const void* src) {
    asm volatile("cp.async.cg.shared.global [%0], [%1], 16;" :: "r"(dst), "l"(src));
}
#define CP_COMMIT() asm volatile("cp.async.commit_group;" ::: "memory")
template <int N> __device__ __forceinline__ void cp_wait() {
    asm volatile("cp.async.wait_group %0;" :: "n"(N) : "memory");
}
__device__ __forceinline__ void ldsm4(uint32_t* d, uint32_t addr) {
    asm volatile("ldmatrix.sync.aligned.m8n8.x4.shared.b16 {%0,%1,%2,%3}, [%4];"
        : "=r"(d[0]), "=r"(d[1]), "=r"(d[2]), "=r"(d[3]) : "r"(addr));
}
__device__ __forceinline__ void ldsm4t(uint32_t* d, uint32_t addr) {
    asm volatile("ldmatrix.sync.aligned.m8n8.x4.trans.shared.b16 {%0,%1,%2,%3}, [%4];"
        : "=r"(d[0]), "=r"(d[1]), "=r"(d[2]), "=r"(d[3]) : "r"(addr));
}
__device__ __forceinline__ void mma16(float* c, const uint32_t* a, const uint32_t* b) {
    asm volatile(
        "mma.sync.aligned.m16n8k16.row.col.f32.f16.f16.f32 "
        "{%0,%1,%2,%3}, {%4,%5,%6,%7}, {%8,%9}, {%0,%1,%2,%3};"
        : "+f"(c[0]), "+f"(c[1]), "+f"(c[2]), "+f"(c[3])
        : "r"(a[0]), "r"(a[1]), "r"(a[2]), "r"(a[3]), "r"(b[0]), "r"(b[1]));
}
__device__ __forceinline__ float fast_exp(float x)
{
    float t  = x * 1.4426950408889634f;
    float kf = rintf(t);
    float rr = fmaf(kf, -0.6931471805599453f, x);
    float p  = fmaf(rr, 0.0083333333f, 0.041666667f);
    p = fmaf(rr, p, 0.16666667f);
    p = fmaf(rr, p, 0.5f);
    p = fmaf(rr, p, 1.0f);
    p = fmaf(rr, p, 1.0f);
    return p * __int_as_float(((int)kf + 127) << 23);
}

// ---------------- fp32 -> fp16 convert ---------------------------------------
__global__ __launch_bounds__(256) void cvt_f2h(const float* __restrict__ s,
                                               __half* __restrict__ d)
{
    int i = (blockIdx.x * 256 + threadIdx.x) * 8;
    float4 a = *(const float4*)(s + i);
    float4 b = *(const float4*)(s + i + 4);
    __half2 h0 = __floats2half2_rn(a.x, a.y), h1 = __floats2half2_rn(a.z, a.w);
    __half2 h2 = __floats2half2_rn(b.x, b.y), h3 = __floats2half2_rn(b.z, b.w);
    uint4 o;
    o.x = *(uint32_t*)&h0; o.y = *(uint32_t*)&h1;
    o.z = *(uint32_t*)&h2; o.w = *(uint32_t*)&h3;
    *(uint4*)(d + i) = o;
}

// ---------------- fp16 NT GEMM (cp.async 3-stage) -----------------------------
#define SA 40
#define GS_A 5120
template <int MODE, bool NORM>
__global__ __launch_bounds__(256, 2) void gemm_f16(
    const __half* __restrict__ A, const __half* __restrict__ Bm,
    const float* __restrict__ bias, void* __restrict__ Cv,
    float* __restrict__ nOut, float* __restrict__ rOut,
    int M, int N, int K, int ntok)
{
    extern __shared__ __half smg[];
    const uint32_t base = (uint32_t)__cvta_generic_to_shared(smg);

    const int tid  = threadIdx.x;
    const int wid  = tid >> 5;
    const int lane = tid & 31;
    const int r    = lane >> 2;
    const int cq   = lane & 3;
    const int wm   = wid & 3;
    const int wn   = wid >> 2;
    const int row0 = blockIdx.y * 128;
    const int col0 = blockIdx.x * 128;

    const int lr  = lane & 7, grp = lane >> 3;
    const int aRO = ((grp & 1) << 3) + lr, aKO = (grp >> 1) << 3;
    const int bRO = ((grp >> 1) << 3) + lr, bKO = (grp & 1) << 3;

    const int crow = tid >> 2;
    const int cseg = (tid & 3) * 8;

    auto issue = [&](int s) {
        int st = s % 3, k0 = s * 32;
        uint32_t dA = base + (st * GS_A) * 2;
        uint32_t dB = base + ((3 + st) * GS_A) * 2;
#pragma unroll
        for (int i = 0; i < 2; i++) {
            int row = crow + i * 64;
            cp16(dA + (row * SA + cseg) * 2, A  + (size_t)(row0 + row) * K + k0 + cseg);
            cp16(dB + (row * SA + cseg) * 2, Bm + (size_t)(col0 + row) * K + k0 + cseg);
        }
    };

    float cr[2][8][4];
#pragma unroll
    for (int mt = 0; mt < 2; mt++)
#pragma unroll
        for (int nt = 0; nt < 8; nt++)
#pragma unroll
            for (int e = 0; e < 4; e++) cr[mt][nt][e] = 0.f;

    const int S = K >> 5;
    issue(0); CP_COMMIT();
    issue(1); CP_COMMIT();

    for (int s = 0; s < S; s++) {
        if (s + 1 < S) cp_wait<1>(); else cp_wait<0>();
        __syncthreads();
        if (s + 2 < S) { issue(s + 2); CP_COMMIT(); }

        const int st = s % 3;
        const uint32_t aO = base + (st * GS_A) * 2;
        const uint32_t bO = base + ((3 + st) * GS_A) * 2;
#pragma unroll
        for (int k16 = 0; k16 < 2; k16++) {
            uint32_t af[2][4];
#pragma unroll
            for (int mt = 0; mt < 2; mt++)
                ldsm4(af[mt], aO + ((wm * 32 + mt * 16 + aRO) * SA + k16 * 16 + aKO) * 2);
            uint32_t bf[8][2];
#pragma unroll
            for (int ntp = 0; ntp < 4; ntp++) {
                uint32_t t[4];
                ldsm4(t, bO + ((wn * 64 + ntp * 16 + bRO) * SA + k16 * 16 + bKO) * 2);
                bf[2 * ntp][0] = t[0]; bf[2 * ntp][1] = t[1];
                bf[2 * ntp + 1][0] = t[2]; bf[2 * ntp + 1][1] = t[3];
            }
#pragma unroll
            for (int mt = 0; mt < 2; mt++)
#pragma unroll
                for (int nt = 0; nt < 8; nt++)
                    mma16(cr[mt][nt], af[mt], bf[nt]);
        }
        __syncthreads();
    }

#pragma unroll
    for (int mt = 0; mt < 2; mt++) {
        const int m1 = row0 + wm * 32 + mt * 16 + r;
        const int m2 = m1 + 8;
        float ss1 = 0.f, ss2 = 0.f;
#pragma unroll
        for (int nt = 0; nt < 8; nt++) {
            const int n = col0 + wn * 64 + nt * 8 + 2 * cq;
            float* cc = cr[mt][nt];
            float bx = bias[n], by = bias[n + 1];
            float v1x = cc[0] + bx, v1y = cc[1] + by;
            float v2x = cc[2] + bx, v2y = cc[3] + by;
            if constexpr (MODE == 0) {
                float* C = (float*)Cv;
                *(float2*)(C + (size_t)m1 * N + n) = make_float2(v1x, v1y);
                *(float2*)(C + (size_t)m2 * N + n) = make_float2(v2x, v2y);
            } else {
                __half* C = (__half*)Cv;
                int h = n >> 6, d0 = n & 63;
                int b1v = m1 / ntok, t1 = m1 - b1v * ntok;
                int b2v = m2 / ntok, t2 = m2 - b2v * ntok;
                __half2 h1 = __floats2half2_rn(v1x, v1y);
                __half2 h2 = __floats2half2_rn(v2x, v2y);
                *(__half2*)(C + (((size_t)(b1v * HH + h)) * ntok + t1) * 64 + d0) = h1;
                *(__half2*)(C + (((size_t)(b2v * HH + h)) * ntok + t2) * 64 + d0) = h2;
                if (NORM) {
                    float r1x = __half2float(__low2half(h1)), r1y = __half2float(__high2half(h1));
                    float r2x = __half2float(__low2half(h2)), r2y = __half2float(__high2half(h2));
                    ss1 = fmaf(r1x, r1x, fmaf(r1y, r1y, ss1));
                    ss2 = fmaf(r2x, r2x, fmaf(r2y, r2y, ss2));
                }
            }
        }
        if (NORM) {
            ss1 += __shfl_xor_sync(0xffffffffu, ss1, 1);
            ss1 += __shfl_xor_sync(0xffffffffu, ss1, 2);
            ss2 += __shfl_xor_sync(0xffffffffu, ss2, 1);
            ss2 += __shfl_xor_sync(0xffffffffu, ss2, 2);
            if (cq == 0) {
                int h = (col0 + wn * 64) >> 6;
                int b1v = m1 / ntok, t1 = m1 - b1v * ntok;
                int b2v = m2 / ntok, t2 = m2 - b2v * ntok;
                size_t i1 = ((size_t)(b1v * HH + h)) * ntok + t1;
                size_t i2 = ((size_t)(b2v * HH + h)) * ntok + t2;
                float n1 = sqrtf(ss1), n2 = sqrtf(ss2);
                nOut[i1] = n1; rOut[i1] = (n1 > 0.f) ? 1.0f / n1 : 0.f;
                nOut[i2] = n2; rOut[i2] = (n2 > 0.f) ? 1.0f / n2 : 0.f;
            }
        }
    }
}

// ---------------- fused attention (cp.async, two-pass) -------------------------
#define AS 72
#define SQ_OFF 0
#define SK_OFF (128 * AS)
#define SV_OFF (SK_OFF + 2 * 64 * AS)
#define SP_OFF (SV_OFF + 2 * 64 * AS)
#define SS_OFF (SP_OFF + 128 * AS)
#define ATTN_SMEM (SS_OFF * 2 + 128 * 4)

__global__ __launch_bounds__(256, 2) void attn_fused(
    const __half* __restrict__ q, const __half* __restrict__ k, const __half* __restrict__ v,
    const float* __restrict__ qn, const float* __restrict__ qnr,
    const float* __restrict__ kn, const float* __restrict__ knr,
    float* __restrict__ att, __half* __restrict__ ho)
{
    extern __shared__ __half smh[];
    __half* sP = smh + SP_OFF;
    float*  sS = (float*)(smh + SS_OFF);

    const uint32_t sQb = (uint32_t)__cvta_generic_to_shared(smh + SQ_OFF);
    const uint32_t sKb = (uint32_t)__cvta_generic_to_shared(smh + SK_OFF);
    const uint32_t sVb = (uint32_t)__cvta_generic_to_shared(smh + SV_OFF);
    const uint32_t sPb = (uint32_t)__cvta_generic_to_shared(sP);

    const int tid  = threadIdx.x;
    const int wid  = tid >> 5;
    const int lane = tid & 31;
    const int r    = lane >> 2;
    const int cq   = lane & 3;
    const int wm   = wid & 3;
    const int wn   = wid >> 2;

    const int bh = blockIdx.y;
    const int t0 = blockIdx.x * 128;
    const int b  = bh >> 3, h = bh & 7;

    const __half* Qp = q + ((size_t)bh * NTOK + t0) * 64;
    const __half* Kp = k + (size_t)bh * NCTX * 64;
    const __half* Vp = v + (size_t)bh * NCTX * 64;
    float* attp = att + ((size_t)bh * NTOK + t0) * NCTX;

    const int lr  = lane & 7, grp = lane >> 3;
    const int aRO = ((grp & 1) << 3) + lr, aKO = (grp >> 1) << 3;
    const int bRO = ((grp >> 1) << 3) + lr, bKO = (grp & 1) << 3;
    const int vRO = ((grp & 1) << 3) + lr, vDO = (grp >> 1) << 3;

    const int crow = tid >> 3;
    const int cseg = (tid & 7) * 8;

    auto issueQ = [&]() {
#pragma unroll
        for (int i = 0; i < 4; i++) {
            int c = tid + i * 256;
            int row = c >> 3, off = (c & 7) * 8;
            cp16(sQb + (row * AS + off) * 2, Qp + (size_t)row * 64 + off);
        }
    };
    auto issueK = [&](int buf, int c0) {
#pragma unroll
        for (int i = 0; i < 2; i++) {
            int row = crow + i * 32;
            cp16(sKb + (buf * 64 * AS + row * AS + cseg) * 2,
                 Kp + (size_t)(c0 + row) * 64 + cseg);
        }
    };
    auto issueV = [&](int buf, int c0) {
#pragma unroll
        for (int i = 0; i < 2; i++) {
            int row = crow + i * 32;
            cp16(sVb + (buf * 64 * AS + row * AS + cseg) * 2,
                 Vp + (size_t)(c0 + row) * 64 + cseg);
        }
    };

    float qnA[2], qrA[2], qnB[2], qrB[2];
#pragma unroll
    for (int mt = 0; mt < 2; mt++) {
        int m1 = wm * 32 + mt * 16 + r;
        qnA[mt] = qn [bh * NTOK + t0 + m1];
        qrA[mt] = qnr[bh * NTOK + t0 + m1];
        qnB[mt] = qn [bh * NTOK + t0 + m1 + 8];
        qrB[mt] = qnr[bh * NTOK + t0 + m1 + 8];
    }

    auto mma1 = [&](int buf, float p[2][4][4]) {
#pragma unroll
        for (int mt = 0; mt < 2; mt++)
#pragma unroll
            for (int nt = 0; nt < 4; nt++)
#pragma unroll
                for (int e = 0; e < 4; e++) p[mt][nt][e] = 0.f;
        const uint32_t kO = sKb + buf * (64 * AS * 2);
#pragma unroll
        for (int k16 = 0; k16 < 4; k16++) {
            uint32_t af[2][4];
#pragma unroll
            for (int mt = 0; mt < 2; mt++)
                ldsm4(af[mt], sQb + ((wm * 32 + mt * 16 + aRO) * AS + k16 * 16 + aKO) * 2);
            uint32_t bf[4][2];
#pragma unroll
            for (int ntp = 0; ntp < 2; ntp++) {
                uint32_t t[4];
                ldsm4(t, kO + ((wn * 32 + ntp * 16 + bRO) * AS + k16 * 16 + bKO) * 2);
                bf[2 * ntp][0] = t[0]; bf[2 * ntp][1] = t[1];
                bf[2 * ntp + 1][0] = t[2]; bf[2 * ntp + 1][1] = t[3];
            }
#pragma unroll
            for (int mt = 0; mt < 2; mt++)
#pragma unroll
                for (int nt = 0; nt < 4; nt++)
                    mma16(p[mt][nt], af[mt], bf[nt]);
        }
    };

    float rsA[2] = {0.f, 0.f}, rsB[2] = {0.f, 0.f};

    // pass 1: row sums
    issueQ(); issueK(0, 0); CP_COMMIT();
    for (int ct = 0; ct < 32; ct++) {
        const int buf = ct & 1;
        cp_wait<0>(); __syncthreads();
        if (ct + 1 < 32) { issueK(buf ^ 1, (ct + 1) * 64); CP_COMMIT(); }
        float p[2][4][4];
        mma1(buf, p);
#pragma unroll
        for (int mt = 0; mt < 2; mt++) {
#pragma unroll
            for (int nt = 0; nt < 4; nt++) {
                int nl = wn * 32 + nt * 8 + 2 * cq;
                int ng = ct * 64 + nl;
                float2 kv = *(const float2*)(kn  + bh * NCTX + ng);
                float2 kr = *(const float2*)(knr + bh * NCTX + ng);
                float* cc = p[mt][nt];
                float i1x = (qnA[mt] * kv.x > EPSV) ? qrA[mt] * kr.x : 1e6f;
                float i1y = (qnA[mt] * kv.y > EPSV) ? qrA[mt] * kr.y : 1e6f;
                float i2x = (qnB[mt] * kv.x > EPSV) ? qrB[mt] * kr.x : 1e6f;
                float i2y = (qnB[mt] * kv.y > EPSV) ? qrB[mt] * kr.y : 1e6f;
                rsA[mt] += fast_exp(cc[0] * i1x) + fast_exp(cc[1] * i1y);
                rsB[mt] += fast_exp(cc[2] * i2x) + fast_exp(cc[3] * i2y);
            }
        }
        __syncthreads();
    }

#pragma unroll
    for (int mt = 0; mt < 2; mt++) {
        rsA[mt] += __shfl_xor_sync(0xffffffffu, rsA[mt], 1);
        rsA[mt] += __shfl_xor_sync(0xffffffffu, rsA[mt], 2);
        rsB[mt] += __shfl_xor_sync(0xffffffffu, rsB[mt], 1);
        rsB[mt] += __shfl_xor_sync(0xffffffffu, rsB[mt], 2);
    }
    if (wn == 0 && cq == 0) {
#pragma unroll
        for (int mt = 0; mt < 2; mt++) {
            int m1 = wm * 32 + mt * 16 + r;
            sS[m1] = rsA[mt]; sS[m1 + 8] = rsB[mt];
        }
    }
    __syncthreads();
    if (wn == 1 && cq == 0) {
#pragma unroll
        for (int mt = 0; mt < 2; mt++) {
            int m1 = wm * 32 + mt * 16 + r;
            sS[m1] += rsA[mt]; sS[m1 + 8] += rsB[mt];
        }
    }
    __syncthreads();
    if (tid < 128) sS[tid] = 1.0f / sS[tid];
    __syncthreads();

    float invA[2], invB[2];
#pragma unroll
    for (int mt = 0; mt < 2; mt++) {
        int m1 = wm * 32 + mt * 16 + r;
        invA[mt] = sS[m1]; invB[mt] = sS[m1 + 8];
    }

    // pass 2: single att write + AV
    float av[2][4][4];
#pragma unroll
    for (int mt = 0; mt < 2; mt++)
#pragma unroll
        for (int nt = 0; nt < 4; nt++)
#pragma unroll
            for (int e = 0; e < 4; e++) av[mt][nt][e] = 0.f;

    issueK(0, 0); issueV(0, 0); CP_COMMIT();

    for (int ct = 0; ct < 32; ct++) {
        const int buf = ct & 1;
        cp_wait<0>(); __syncthreads();
        if (ct + 1 < 32) { issueK(buf ^ 1, (ct + 1) * 64); issueV(buf ^ 1, (ct + 1) * 64); CP_COMMIT(); }

        float p[2][4][4];
        mma1(buf, p);

#pragma unroll
        for (int mt = 0; mt < 2; mt++) {
            int m1 = wm * 32 + mt * 16 + r, m2 = m1 + 8;
#pragma unroll
            for (int nt = 0; nt < 4; nt++) {
                int nl = wn * 32 + nt * 8 + 2 * cq;
                int ng = ct * 64 + nl;
                float2 kv = *(const float2*)(kn  + bh * NCTX + ng);
                float2 kr = *(const float2*)(knr + bh * NCTX + ng);
                float* cc = p[mt][nt];
                float i1x = (qnA[mt] * kv.x > EPSV) ? qrA[mt] * kr.x : 1e6f;
                float i1y = (qnA[mt] * kv.y > EPSV) ? qrA[mt] * kr.y : 1e6f;
                float i2x = (qnB[mt] * kv.x > EPSV) ? qrB[mt] * kr.x : 1e6f;
                float i2y = (qnB[mt] * kv.y > EPSV) ? qrB[mt] * kr.y : 1e6f;
                float e0 = fast_exp(cc[0] * i1x);
                float e1 = fast_exp(cc[1] * i1y);
                float e2 = fast_exp(cc[2] * i2x);
                float e3 = fast_exp(cc[3] * i2y);
                __stcs((float2*)(attp + (size_t)m1 * NCTX + ng),
                       make_float2(e0 * invA[mt], e1 * invA[mt]));
                __stcs((float2*)(attp + (size_t)m2 * NCTX + ng),
                       make_float2(e2 * invB[mt], e3 * invB[mt]));
                *(__half2*)&sP[m1 * AS + nl] = __floats2half2_rn(e0, e1);
                *(__half2*)&sP[m2 * AS + nl] = __floats2half2_rn(e2, e3);
            }
        }
        __syncthreads();

        const uint32_t vO = sVb + buf * (64 * AS * 2);
#pragma unroll
        for (int k16 = 0; k16 < 4; k16++) {
            uint32_t af[2][4];
#pragma unroll
            for (int mt = 0; mt < 2; mt++)
                ldsm4(af[mt], sPb + ((wm * 32 + mt * 16 + aRO) * AS + k16 * 16 + aKO) * 2);
            uint32_t bf[4][2];
#pragma unroll
            for (int ntp = 0; ntp < 2; ntp++) {
                uint32_t t[4];
                ldsm4t(t, vO + ((k16 * 16 + vRO) * AS + wn * 32 + ntp * 16 + vDO) * 2);
                bf[2 * ntp][0] = t[0]; bf[2 * ntp][1] = t[1];
                bf[2 * ntp + 1][0] = t[2]; bf[2 * ntp + 1][1] = t[3];
            }
#pragma unroll
            for (int mt = 0; mt < 2; mt++)
#pragma unroll
                for (int nt = 0; nt < 4; nt++)
                    mma16(av[mt][nt], af[mt], bf[nt]);
        }
    }

    // write AV -> ho (fp16)
#pragma unroll
    for (int mt = 0; mt < 2; mt++) {
        int m1 = wm * 32 + mt * 16 + r, m2 = m1 + 8;
#pragma unroll
        for (int nt = 0; nt < 4; nt++) {
            int d0 = wn * 32 + nt * 8 + 2 * cq;
            float* cc = av[mt][nt];
            *(__half2*)(ho + (((size_t)(b * NTOK + t0 + m1)) * HH + h) * 64 + d0) =
                __floats2half2_rn(cc[0] * invA[mt], cc[1] * invA[mt]);
            *(__half2*)(ho + (((size_t)(b * NTOK + t0 + m2)) * HH + h) * 64 + d0) =
                __floats2half2_rn(cc[2] * invB[mt], cc[3] * invB[mt]);
        }
    }
}

// ---------------- launch -----------------------------------------------------
extern "C" void kernel_launch(void* const* d_in, const int* in_sizes, int n_in,
                              void* d_out, int out_size)
{
    const float* queries = (const float*)d_in[0];
    const float* keys    = (const float*)d_in[1];
    const float* values  = (const float*)d_in[2];
    const float* W_At    = (const float*)d_in[3];
    const float* b_At    = (const float*)d_in[4];
    const float* W_Ac    = (const float*)d_in[5];
    const float* b_Ac    = (const float*)d_in[6];
    const float* W_Bc    = (const float*)d_in[7];
    const float* b_Bc    = (const float*)d_in[8];
    const float* W_R     = (const float*)d_in[9];
    const float* b_R     = (const float*)d_in[10];

    float* out = (float*)d_out;
    float* att = out + OUT_ELEMS;

    __half *xq, *xk, *xv, *wat, *wac, *wbc, *wr, *q, *k, *v, *ho;
    float *qn, *qnr, *kn, *knr;
    cudaGetSymbolAddress((void**)&xq,  g_xq);
    cudaGetSymbolAddress((void**)&xk,  g_xk);
    cudaGetSymbolAddress((void**)&xv,  g_xv);
    cudaGetSymbolAddress((void**)&wat, g_wat);
    cudaGetSymbolAddress((void**)&wac, g_wac);
    cudaGetSymbolAddress((void**)&wbc, g_wbc);
    cudaGetSymbolAddress((void**)&wr,  g_wr);
    cudaGetSymbolAddress((void**)&q,   g_q);
    cudaGetSymbolAddress((void**)&k,   g_k);
    cudaGetSymbolAddress((void**)&v,   g_v);
    cudaGetSymbolAddress((void**)&ho,  g_ho);
    cudaGetSymbolAddress((void**)&qn,  g_qn);
    cudaGetSymbolAddress((void**)&qnr, g_qnr);
    cudaGetSymbolAddress((void**)&kn,  g_kn);
    cudaGetSymbolAddress((void**)&knr, g_knr);

    const int GEMM_SMEM = 6 * GS_A * 2;
    cudaFuncSetAttribute(gemm_f16<0, false>, cudaFuncAttributeMaxDynamicSharedMemorySize, GEMM_SMEM);
    cudaFuncSetAttribute(gemm_f16<1, false>, cudaFuncAttributeMaxDynamicSharedMemorySize, GEMM_SMEM);
    cudaFuncSetAttribute(gemm_f16<1, true >, cudaFuncAttributeMaxDynamicSharedMemorySize, GEMM_SMEM);
    cudaFuncSetAttribute(attn_fused, cudaFuncAttributeMaxDynamicSharedMemorySize, ATTN_SMEM);

    cvt_f2h<<<(B_ * NTOK * EMBD) / 2048, 256>>>(queries, xq);
    cvt_f2h<<<(B_ * NCTX * EMBD) / 2048, 256>>>(keys,    xk);
    cvt_f2h<<<(B_ * NCTX * EMBD) / 2048, 256>>>(values,  xv);
    cvt_f2h<<<(EMBD * EMBD) / 2048, 256>>>(W_At, wat);
    cvt_f2h<<<(EMBD * EMBD) / 2048, 256>>>(W_Ac, wac);
    cvt_f2h<<<(EMBD * EMBD) / 2048, 256>>>(W_Bc, wbc);
    cvt_f2h<<<(EMBD * EMBD) / 2048, 256>>>(W_R,  wr);

    gemm_f16<1, true ><<<dim3(4, 32),  256, GEMM_SMEM>>>(xq, wat, b_At, q, qn, qnr, B_ * NTOK, HH * DKV, EMBD, NTOK);
    gemm_f16<1, true ><<<dim3(4, 128), 256, GEMM_SMEM>>>(xk, wac, b_Ac, k, kn, knr, B_ * NCTX, HH * DKV, EMBD, NCTX);
    gemm_f16<1, false><<<dim3(4, 128), 256, GEMM_SMEM>>>(xv, wbc, b_Bc, v, nullptr, nullptr, B_ * NCTX, HH * DKV, EMBD, NCTX);

    attn_fused<<<dim3(4, 64), 256, ATTN_SMEM>>>(q, k, v, qn, qnr, kn, knr, att, ho);

    gemm_f16<0, false><<<dim3(4, 32), 256, GEMM_SMEM>>>(ho, wr, b_R, out, nullptr, nullptr, B_ * NTOK, EMBD, HH * DKV, 0);
}